// round 2
// baseline (speedup 1.0000x reference)
#include <cuda_runtime.h>
#include <math.h>

// Problem dims
#define B_   4
#define N_   1024
#define D_   512
#define DK_  512
#define DV_  512
#define NH_  8
#define HD_  64          // head dim
#define M_   (B_ * N_)   // 4096 rows

#define SCALE_ 0.04419417382415922f   // 1/sqrt(512)

// ---------------- device scratch (no allocations allowed) ----------------
__device__ float g_c[M_ * D_];   // layernorm output
__device__ float g_q[M_ * DK_];
__device__ float g_k[M_ * DK_];
__device__ float g_v[M_ * DV_];

// ---------------- LayerNorm: one block per row ----------------
__global__ void __launch_bounds__(256) ln_kernel(const float* __restrict__ x,
                                                 const float* __restrict__ gamma,
                                                 const float* __restrict__ beta) {
    int row = blockIdx.x;
    int t = threadIdx.x;
    const float* xr = x + (size_t)row * D_;
    float v0 = xr[t], v1 = xr[t + 256];
    float s = v0 + v1;
    float sq = v0 * v0 + v1 * v1;
#pragma unroll
    for (int o = 16; o; o >>= 1) {
        s  += __shfl_xor_sync(0xffffffffu, s,  o);
        sq += __shfl_xor_sync(0xffffffffu, sq, o);
    }
    __shared__ float shs[8], shq[8];
    if ((t & 31) == 0) { shs[t >> 5] = s; shq[t >> 5] = sq; }
    __syncthreads();
    s = 0.f; sq = 0.f;
#pragma unroll
    for (int i = 0; i < 8; i++) { s += shs[i]; sq += shq[i]; }
    float mean = s * (1.0f / 512.0f);
    float var  = sq * (1.0f / 512.0f) - mean * mean;
    float rstd = rsqrtf(var + 1e-5f);
    float* o = g_c + (size_t)row * D_;
    o[t]       = (v0 - mean) * rstd * gamma[t]       + beta[t];
    o[t + 256] = (v1 - mean) * rstd * gamma[t + 256] + beta[t + 256];
}

// ---------------- fused QKV GEMM: out = A @ W^T + bias ----------------
// blockIdx.z: 0 -> q = c@Wq^T+bq, 1 -> k = c@Wk^T+bk, 2 -> v = exo@Wv^T+bv
// 128x128 block tile, BK=16, 256 threads, 8x8 per-thread microtile.
__global__ void __launch_bounds__(256) gemm_qkv_kernel(
    const float* __restrict__ exo,
    const float* __restrict__ Wq, const float* __restrict__ bq,
    const float* __restrict__ Wk, const float* __restrict__ bk,
    const float* __restrict__ Wv, const float* __restrict__ bv) {

    const float* A; const float* W; const float* bias; float* O;
    int z = blockIdx.z;
    if (z == 0)      { A = g_c; W = Wq; bias = bq; O = g_q; }
    else if (z == 1) { A = g_c; W = Wk; bias = bk; O = g_k; }
    else             { A = exo; W = Wv; bias = bv; O = g_v; }

    __shared__ float As[16][132];   // transposed: As[k][m], pad keeps f4 alignment
    __shared__ float Bs[16][132];   // Bs[k][n]

    int tid = threadIdx.x;
    int bm = blockIdx.y * 128;
    int bn = blockIdx.x * 128;

    float acc[8][8];
#pragma unroll
    for (int i = 0; i < 8; i++)
#pragma unroll
        for (int j = 0; j < 8; j++) acc[i][j] = 0.f;

    int rA = tid >> 2;            // 0..63
    int c4 = (tid & 3) * 4;       // 0,4,8,12
    int rm = (tid >> 4) * 8;      // row offset of microtile
    int rn = (tid & 15) * 8;      // col offset of microtile

    for (int k0 = 0; k0 < 512; k0 += 16) {
#pragma unroll
        for (int u = 0; u < 2; u++) {
            int r = rA + u * 64;
            float4 av = *(const float4*)(A + (size_t)(bm + r) * 512 + k0 + c4);
            As[c4 + 0][r] = av.x; As[c4 + 1][r] = av.y;
            As[c4 + 2][r] = av.z; As[c4 + 3][r] = av.w;
            float4 wv = *(const float4*)(W + (size_t)(bn + r) * 512 + k0 + c4);
            Bs[c4 + 0][r] = wv.x; Bs[c4 + 1][r] = wv.y;
            Bs[c4 + 2][r] = wv.z; Bs[c4 + 3][r] = wv.w;
        }
        __syncthreads();
#pragma unroll
        for (int kk = 0; kk < 16; kk++) {
            float4 a0 = *(const float4*)&As[kk][rm];
            float4 a1 = *(const float4*)&As[kk][rm + 4];
            float4 b0 = *(const float4*)&Bs[kk][rn];
            float4 b1 = *(const float4*)&Bs[kk][rn + 4];
            float a[8] = {a0.x, a0.y, a0.z, a0.w, a1.x, a1.y, a1.z, a1.w};
            float b[8] = {b0.x, b0.y, b0.z, b0.w, b1.x, b1.y, b1.z, b1.w};
#pragma unroll
            for (int i = 0; i < 8; i++)
#pragma unroll
                for (int j = 0; j < 8; j++)
                    acc[i][j] = fmaf(a[i], b[j], acc[i][j]);
        }
        __syncthreads();
    }
#pragma unroll
    for (int i = 0; i < 8; i++) {
        float* orow = O + (size_t)(bm + rm + i) * 512 + bn + rn;
#pragma unroll
        for (int j = 0; j < 8; j++) orow[j] = acc[i][j] + bias[bn + rn + j];
    }
}

// ---------------- attention: one block per (b, h, 32-row q tile) ----------------
// smem: q tile 32x64 | k/v staging 64x65 | scores 32x1024  => ~152 KB dynamic
__global__ void __launch_bounds__(256) attn_kernel(const float* __restrict__ adj,
                                                   float* __restrict__ att,
                                                   float* __restrict__ dist) {
    extern __shared__ float sm[];
    float* qs  = sm;                    // 2048
    float* kvs = sm + 2048;             // 64*65 = 4160 (K transposed / V plain)
    float* sc  = sm + 2048 + 4160;      // 32*1024 = 32768

    int qt = blockIdx.x, h = blockIdx.y, b = blockIdx.z;
    int n0 = qt * 32;
    int tid = threadIdx.x;
    int tx = tid & 31, ty = tid >> 5;

    // load q tile [32 x 64] (float4)
#pragma unroll
    for (int u = 0; u < 2; u++) {
        int idx = tid + u * 256;        // float4 index, 0..511
        int i  = idx >> 4;              // 0..31
        int d4 = (idx & 15) * 4;
        float4 qv = *(const float4*)(g_q + (size_t)(b * N_ + n0 + i) * DK_ + h * HD_ + d4);
        *(float4*)(qs + i * 64 + d4) = qv;
    }

    // ---- scores: sc[i][m] = scale * q_i . k_m ----
    for (int kt = 0; kt < 16; kt++) {
        __syncthreads();   // protect kvs reuse + (first iter) qs visibility
        // K tile transposed: kvs[d*65 + j]
#pragma unroll
        for (int u = 0; u < 4; u++) {
            int idx = tid + u * 256;    // 0..1023 f4
            int j  = idx >> 4;          // 0..63
            int d4 = (idx & 15) * 4;
            float4 kv4 = *(const float4*)(g_k + (size_t)(b * N_ + kt * 64 + j) * DK_ + h * HD_ + d4);
            kvs[(d4 + 0) * 65 + j] = kv4.x;
            kvs[(d4 + 1) * 65 + j] = kv4.y;
            kvs[(d4 + 2) * 65 + j] = kv4.z;
            kvs[(d4 + 3) * 65 + j] = kv4.w;
        }
        __syncthreads();
        float acc[4][2] = {};
#pragma unroll 8
        for (int d = 0; d < 64; d++) {
            float k0 = kvs[d * 65 + tx];
            float k1 = kvs[d * 65 + tx + 32];
#pragma unroll
            for (int ii = 0; ii < 4; ii++) {
                float qv = qs[(ty + ii * 8) * 64 + d];
                acc[ii][0] = fmaf(qv, k0, acc[ii][0]);
                acc[ii][1] = fmaf(qv, k1, acc[ii][1]);
            }
        }
#pragma unroll
        for (int ii = 0; ii < 4; ii++) {
            sc[(ty + ii * 8) * 1024 + kt * 64 + tx]      = acc[ii][0] * SCALE_;
            sc[(ty + ii * 8) * 1024 + kt * 64 + tx + 32] = acc[ii][1] * SCALE_;
        }
    }
    __syncthreads();

    // ---- softmax (max-subtract) + adj mask + dist write; warp ty: rows ty+8*rr ----
    float* distb = dist + (size_t)(b * NH_ + h) * N_ * N_;
#pragma unroll
    for (int rr = 0; rr < 4; rr++) {
        int r = ty + rr * 8;
        float* srow = sc + r * 1024;
        float mx = -3.402823466e38f;
        for (int c = tx; c < 1024; c += 32) mx = fmaxf(mx, srow[c]);
#pragma unroll
        for (int o = 16; o; o >>= 1) mx = fmaxf(mx, __shfl_xor_sync(0xffffffffu, mx, o));
        float s = 0.f;
        for (int c = tx; c < 1024; c += 32) {
            float e = __expf(srow[c] - mx);
            srow[c] = e;
            s += e;
        }
#pragma unroll
        for (int o = 16; o; o >>= 1) s += __shfl_xor_sync(0xffffffffu, s, o);
        float inv = 1.0f / s;
        const float* arow = adj + (size_t)(n0 + r) * 1024;
        float* drow = distb + (size_t)(n0 + r) * 1024;
        for (int c = tx; c < 1024; c += 32) {
            float p = srow[c] * inv * arow[c];
            srow[c] = p;       // keep masked dist in smem for att GEMM
            drow[c] = p;       // coalesced dist output
        }
    }

    // ---- att[i][d] = sum_m dist[i][m] * v[m][d] ----
    float at[4][2] = {};
    for (int vt = 0; vt < 16; vt++) {
        __syncthreads();   // also serves as softmax->att barrier on first iter
#pragma unroll
        for (int u = 0; u < 4; u++) {
            int idx = tid + u * 256;
            int mrow = idx >> 4;
            int d4 = (idx & 15) * 4;
            float4 vv = *(const float4*)(g_v + (size_t)(b * N_ + vt * 64 + mrow) * DV_ + h * HD_ + d4);
            *(float4*)(kvs + mrow * 64 + d4) = vv;
        }
        __syncthreads();
#pragma unroll 8
        for (int mm = 0; mm < 64; mm++) {
            float v0 = kvs[mm * 64 + tx];
            float v1 = kvs[mm * 64 + tx + 32];
#pragma unroll
            for (int ii = 0; ii < 4; ii++) {
                float p = sc[(ty + ii * 8) * 1024 + vt * 64 + mm];
                at[ii][0] = fmaf(p, v0, at[ii][0]);
                at[ii][1] = fmaf(p, v1, at[ii][1]);
            }
        }
    }
#pragma unroll
    for (int ii = 0; ii < 4; ii++) {
        int n = n0 + ty + ii * 8;
        float* arow = att + (size_t)(b * N_ + n) * DV_ + h * HD_;
        arow[tx]      = at[ii][0];
        arow[tx + 32] = at[ii][1];
    }
}

// ---------------- launch ----------------
extern "C" void kernel_launch(void* const* d_in, const int* in_sizes, int n_in,
                              void* d_out, int out_size) {
    const float* user_exo = (const float*)d_in[0];
    const float* exo      = (const float*)d_in[1];
    const float* adj      = (const float*)d_in[2];
    const float* Wq       = (const float*)d_in[3];
    const float* bq       = (const float*)d_in[4];
    const float* Wk       = (const float*)d_in[5];
    const float* bk       = (const float*)d_in[6];
    const float* Wv       = (const float*)d_in[7];
    const float* bv       = (const float*)d_in[8];
    const float* gamma    = (const float*)d_in[9];
    const float* beta     = (const float*)d_in[10];

    float* att  = (float*)d_out;                       // [B, N, DV]
    float* dist = att + (size_t)B_ * N_ * DV_;         // [B, NH, N, N]

    const int smem_bytes = (2048 + 64 * 65 + 32 * 1024) * (int)sizeof(float);  // 155904
    cudaFuncSetAttribute(attn_kernel, cudaFuncAttributeMaxDynamicSharedMemorySize, smem_bytes);

    ln_kernel<<<M_, 256>>>(user_exo, gamma, beta);
    gemm_qkv_kernel<<<dim3(4, 32, 3), 256>>>(exo, Wq, bq, Wk, bk, Wv, bv);
    attn_kernel<<<dim3(N_ / 32, NH_, B_), 256, smem_bytes>>>(adj, att, dist);
}

// round 3
// speedup vs baseline: 1.5110x; 1.5110x over previous
#include <cuda_runtime.h>
#include <math.h>
#include <stdint.h>

// Problem dims
#define B_   4
#define N_   1024
#define D_   512
#define NH_  8
#define M_   (B_ * N_)   // 4096 rows

#define SCALE_ 0.04419417382415922f   // 1/sqrt(512)

// ---------------- device scratch (no allocations allowed) ----------------
__device__ float g_c[M_ * D_];   // layernorm output
__device__ float g_q[M_ * D_];
__device__ float g_k[M_ * D_];
__device__ float g_v[M_ * D_];

// ---------------- tf32 helpers ----------------
__device__ __forceinline__ void tf32_split(float v, float& hi, float& lo) {
    uint32_t u;
    asm("cvt.rna.tf32.f32 %0, %1;" : "=r"(u) : "f"(v));
    hi = __uint_as_float(u);
    asm("cvt.rna.tf32.f32 %0, %1;" : "=r"(u) : "f"(v - hi));
    lo = __uint_as_float(u);
}

__device__ __forceinline__ void mma8(float d[4], const float a[4], const float b[2]) {
    asm volatile("mma.sync.aligned.m16n8k8.row.col.f32.tf32.tf32.f32 "
        "{%0,%1,%2,%3},{%4,%5,%6,%7},{%8,%9},{%0,%1,%2,%3};"
        : "+f"(d[0]), "+f"(d[1]), "+f"(d[2]), "+f"(d[3])
        : "r"(__float_as_uint(a[0])), "r"(__float_as_uint(a[1])),
          "r"(__float_as_uint(a[2])), "r"(__float_as_uint(a[3])),
          "r"(__float_as_uint(b[0])), "r"(__float_as_uint(b[1])));
}

// ---------------- LayerNorm: one block per row ----------------
__global__ void __launch_bounds__(256) ln_kernel(const float* __restrict__ x,
                                                 const float* __restrict__ gamma,
                                                 const float* __restrict__ beta) {
    int row = blockIdx.x;
    int t = threadIdx.x;
    const float* xr = x + (size_t)row * D_;
    float v0 = xr[t], v1 = xr[t + 256];
    float s = v0 + v1;
    float sq = v0 * v0 + v1 * v1;
#pragma unroll
    for (int o = 16; o; o >>= 1) {
        s  += __shfl_xor_sync(0xffffffffu, s,  o);
        sq += __shfl_xor_sync(0xffffffffu, sq, o);
    }
    __shared__ float shs[8], shq[8];
    if ((t & 31) == 0) { shs[t >> 5] = s; shq[t >> 5] = sq; }
    __syncthreads();
    s = 0.f; sq = 0.f;
#pragma unroll
    for (int i = 0; i < 8; i++) { s += shs[i]; sq += shq[i]; }
    float mean = s * (1.0f / 512.0f);
    float var  = sq * (1.0f / 512.0f) - mean * mean;
    float rstd = rsqrtf(var + 1e-5f);
    float* o = g_c + (size_t)row * D_;
    o[t]       = (v0 - mean) * rstd * gamma[t]       + beta[t];
    o[t + 256] = (v1 - mean) * rstd * gamma[t + 256] + beta[t + 256];
}

// ---------------- QKV GEMM via split-TF32 mma (3x) ----------------
// out = A @ W^T + bias.  z: 0->q(c,Wq), 1->k(c,Wk), 2->v(exo,Wv)
// 128x128 block tile, BK=32, 8 warps (warp tile 64x32).
#define GP 36   // smem row stride (32 + 4 pad): conflict-free frags & f4 stores
__global__ void __launch_bounds__(256) gemm_qkv_tc(
    const float* __restrict__ exo,
    const float* __restrict__ Wq, const float* __restrict__ bq,
    const float* __restrict__ Wk, const float* __restrict__ bk,
    const float* __restrict__ Wv, const float* __restrict__ bv) {

    extern __shared__ float sg[];
    float* Ah = sg;                  // [128][36]
    float* Al = Ah + 128 * GP;
    float* Bh = Al + 128 * GP;
    float* Bl = Bh + 128 * GP;

    const float* A; const float* W; const float* bias; float* O;
    int z = blockIdx.z;
    if (z == 0)      { A = g_c; W = Wq; bias = bq; O = g_q; }
    else if (z == 1) { A = g_c; W = Wk; bias = bk; O = g_k; }
    else             { A = exo; W = Wv; bias = bv; O = g_v; }

    int tid = threadIdx.x;
    int lane = tid & 31, wid = tid >> 5;
    int wm = (wid & 1) * 64, wn = (wid >> 1) * 32;
    int qr = lane >> 2, qc = lane & 3;
    int bm = blockIdx.y * 128, bn = blockIdx.x * 128;

    float C[4][4][4] = {};

    int lr = tid >> 3;            // 0..31
    int lc4 = (tid & 7) * 4;      // 0,4..28

    for (int k0 = 0; k0 < 512; k0 += 32) {
        __syncthreads();
#pragma unroll
        for (int u = 0; u < 4; u++) {
            int r = lr + u * 32;
            float4 av = *(const float4*)(A + (size_t)(bm + r) * 512 + k0 + lc4);
            float4 wv = *(const float4*)(W + (size_t)(bn + r) * 512 + k0 + lc4);
            float4 ah4, al4, bh4, bl4;
            tf32_split(av.x, ah4.x, al4.x);
            tf32_split(av.y, ah4.y, al4.y);
            tf32_split(av.z, ah4.z, al4.z);
            tf32_split(av.w, ah4.w, al4.w);
            tf32_split(wv.x, bh4.x, bl4.x);
            tf32_split(wv.y, bh4.y, bl4.y);
            tf32_split(wv.z, bh4.z, bl4.z);
            tf32_split(wv.w, bh4.w, bl4.w);
            *(float4*)&Ah[r * GP + lc4] = ah4;
            *(float4*)&Al[r * GP + lc4] = al4;
            *(float4*)&Bh[r * GP + lc4] = bh4;
            *(float4*)&Bl[r * GP + lc4] = bl4;
        }
        __syncthreads();
#pragma unroll
        for (int kk = 0; kk < 4; kk++) {
            int kb = kk * 8;
            float ah[4][4], al[4][4];
#pragma unroll
            for (int mf = 0; mf < 4; mf++) {
                int m = wm + mf * 16;
                ah[mf][0] = Ah[(m + qr) * GP + kb + qc];
                ah[mf][1] = Ah[(m + qr + 8) * GP + kb + qc];
                ah[mf][2] = Ah[(m + qr) * GP + kb + qc + 4];
                ah[mf][3] = Ah[(m + qr + 8) * GP + kb + qc + 4];
                al[mf][0] = Al[(m + qr) * GP + kb + qc];
                al[mf][1] = Al[(m + qr + 8) * GP + kb + qc];
                al[mf][2] = Al[(m + qr) * GP + kb + qc + 4];
                al[mf][3] = Al[(m + qr + 8) * GP + kb + qc + 4];
            }
            float bhf[4][2], blf[4][2];
#pragma unroll
            for (int nf = 0; nf < 4; nf++) {
                int n = wn + nf * 8;
                bhf[nf][0] = Bh[(n + qr) * GP + kb + qc];
                bhf[nf][1] = Bh[(n + qr) * GP + kb + qc + 4];
                blf[nf][0] = Bl[(n + qr) * GP + kb + qc];
                blf[nf][1] = Bl[(n + qr) * GP + kb + qc + 4];
            }
#pragma unroll
            for (int mf = 0; mf < 4; mf++)
#pragma unroll
                for (int nf = 0; nf < 4; nf++) {
                    mma8(C[mf][nf], ah[mf], bhf[nf]);
                    mma8(C[mf][nf], ah[mf], blf[nf]);
                    mma8(C[mf][nf], al[mf], bhf[nf]);
                }
        }
    }
#pragma unroll
    for (int mf = 0; mf < 4; mf++)
#pragma unroll
        for (int nf = 0; nf < 4; nf++) {
            int row = bm + wm + mf * 16 + qr;
            int col = bn + wn + nf * 8 + 2 * qc;
            float2 bv2 = *(const float2*)(bias + col);
            float2 o0 = make_float2(C[mf][nf][0] + bv2.x, C[mf][nf][1] + bv2.y);
            float2 o1 = make_float2(C[mf][nf][2] + bv2.x, C[mf][nf][3] + bv2.y);
            *(float2*)(O + (size_t)row * 512 + col) = o0;
            *(float2*)(O + (size_t)(row + 8) * 512 + col) = o1;
        }
}

// ---------------- attention via split-TF32 mma ----------------
// one block per (b, h, 32-row q tile); 8 warps.
#define QP  68     // Q smem stride [32][68]
#define KP  68     // K tile stride [128][68] (n-major)
#define VP  72     // V tile stride [128][72] (m-major)
#define SCP 1036   // score row stride (1024 + 12)
__global__ void __launch_bounds__(256) attn_tc(const float* __restrict__ adj,
                                               float* __restrict__ att,
                                               float* __restrict__ dist) {
    extern __shared__ float sm[];
    float* Qh  = sm;                    // 32*68   = 2176
    float* Ql  = Qh + 32 * QP;          // 2176
    float* KVh = Ql + 32 * QP;          // 128*72  = 9216
    float* KVl = KVh + 128 * VP;        // 9216
    float* sc  = KVl + 128 * VP;        // 32*1036 = 33152

    int qt = blockIdx.x, h = blockIdx.y, b = blockIdx.z;
    int n0 = qt * 32;
    int tid = threadIdx.x;
    int lane = tid & 31, wid = tid >> 5;
    int qr = lane >> 2, qc = lane & 3;

    // ---- stage Q (pre-scaled) hi/lo ----
#pragma unroll
    for (int u = 0; u < 2; u++) {
        int idx = tid + u * 256;        // f4 units 0..511
        int m = idx >> 4;               // 0..31
        int k4 = (idx & 15) * 4;
        float4 qv = *(const float4*)(g_q + (size_t)(b * N_ + n0 + m) * 512 + h * 64 + k4);
        float4 hv, lv;
        tf32_split(qv.x * SCALE_, hv.x, lv.x);
        tf32_split(qv.y * SCALE_, hv.y, lv.y);
        tf32_split(qv.z * SCALE_, hv.z, lv.z);
        tf32_split(qv.w * SCALE_, hv.w, lv.w);
        *(float4*)&Qh[m * QP + k4] = hv;
        *(float4*)&Ql[m * QP + k4] = lv;
    }
    __syncthreads();

    // ---- preload Q hi fragments into registers (64 regs) ----
    float qh[2][8][4];
#pragma unroll
    for (int mf = 0; mf < 2; mf++)
#pragma unroll
        for (int ks = 0; ks < 8; ks++) {
            int m = mf * 16, kb = ks * 8;
            qh[mf][ks][0] = Qh[(m + qr) * QP + kb + qc];
            qh[mf][ks][1] = Qh[(m + qr + 8) * QP + kb + qc];
            qh[mf][ks][2] = Qh[(m + qr) * QP + kb + qc + 4];
            qh[mf][ks][3] = Qh[(m + qr + 8) * QP + kb + qc + 4];
        }

    // ---- phase 1: scores S[32,1024] = Qs . K^T ----
    for (int kt = 0; kt < 8; kt++) {
        __syncthreads();
#pragma unroll
        for (int u = 0; u < 8; u++) {
            int idx = tid + u * 256;    // f4 units 0..2047
            int n = idx >> 4;           // 0..127
            int k4 = (idx & 15) * 4;
            float4 kv = *(const float4*)(g_k + (size_t)(b * N_ + kt * 128 + n) * 512 + h * 64 + k4);
            float4 hv, lv;
            tf32_split(kv.x, hv.x, lv.x);
            tf32_split(kv.y, hv.y, lv.y);
            tf32_split(kv.z, hv.z, lv.z);
            tf32_split(kv.w, hv.w, lv.w);
            *(float4*)&KVh[n * KP + k4] = hv;
            *(float4*)&KVl[n * KP + k4] = lv;
        }
        __syncthreads();
        float C[2][2][4] = {};
#pragma unroll
        for (int ks = 0; ks < 8; ks++) {
            int kb = ks * 8;
            float al[2][4];
#pragma unroll
            for (int mf = 0; mf < 2; mf++) {
                int m = mf * 16;
                al[mf][0] = Ql[(m + qr) * QP + kb + qc];
                al[mf][1] = Ql[(m + qr + 8) * QP + kb + qc];
                al[mf][2] = Ql[(m + qr) * QP + kb + qc + 4];
                al[mf][3] = Ql[(m + qr + 8) * QP + kb + qc + 4];
            }
            float bh2[2][2], bl2[2][2];
#pragma unroll
            for (int nf = 0; nf < 2; nf++) {
                int n = wid * 16 + nf * 8;
                bh2[nf][0] = KVh[(n + qr) * KP + kb + qc];
                bh2[nf][1] = KVh[(n + qr) * KP + kb + qc + 4];
                bl2[nf][0] = KVl[(n + qr) * KP + kb + qc];
                bl2[nf][1] = KVl[(n + qr) * KP + kb + qc + 4];
            }
#pragma unroll
            for (int mf = 0; mf < 2; mf++)
#pragma unroll
                for (int nf = 0; nf < 2; nf++) {
                    mma8(C[mf][nf], qh[mf][ks], bh2[nf]);
                    mma8(C[mf][nf], qh[mf][ks], bl2[nf]);
                    mma8(C[mf][nf], al[mf], bh2[nf]);
                }
        }
#pragma unroll
        for (int mf = 0; mf < 2; mf++)
#pragma unroll
            for (int nf = 0; nf < 2; nf++) {
                int row = mf * 16 + qr;
                int colg = kt * 128 + wid * 16 + nf * 8 + 2 * qc;
                *(float2*)&sc[row * SCP + colg]       = make_float2(C[mf][nf][0], C[mf][nf][1]);
                *(float2*)&sc[(row + 8) * SCP + colg] = make_float2(C[mf][nf][2], C[mf][nf][3]);
            }
    }
    __syncthreads();

    // ---- softmax + adj mask + dist write (warp wid: rows wid + 8*rr) ----
    float* distb = dist + (size_t)(b * NH_ + h) * N_ * N_;
#pragma unroll
    for (int rr = 0; rr < 4; rr++) {
        int r = wid + rr * 8;
        float* srow = sc + r * SCP;
        float mx = -3.402823466e38f;
        for (int c = lane; c < 1024; c += 32) mx = fmaxf(mx, srow[c]);
#pragma unroll
        for (int o = 16; o; o >>= 1) mx = fmaxf(mx, __shfl_xor_sync(0xffffffffu, mx, o));
        float s = 0.f;
        for (int c = lane; c < 1024; c += 32) {
            float e = __expf(srow[c] - mx);
            srow[c] = e;
            s += e;
        }
#pragma unroll
        for (int o = 16; o; o >>= 1) s += __shfl_xor_sync(0xffffffffu, s, o);
        float inv = 1.0f / s;
        const float* arow = adj + (size_t)(n0 + r) * 1024;
        float* drow = distb + (size_t)(n0 + r) * 1024;
        for (int c = lane; c < 1024; c += 32) {
            float p = srow[c] * inv * arow[c];
            srow[c] = p;       // keep masked dist in smem for P.V
            drow[c] = p;       // coalesced dist output
        }
    }

    // ---- phase 3: att[32,64] = P . V  (warp wid owns k rows wid*16.. of each tile) ----
    float acc[2][8][4] = {};
    for (int vt = 0; vt < 8; vt++) {
        __syncthreads();
#pragma unroll
        for (int u = 0; u < 8; u++) {
            int idx = tid + u * 256;
            int m = idx >> 4;
            int k4 = (idx & 15) * 4;
            float4 vv = *(const float4*)(g_v + (size_t)(b * N_ + vt * 128 + m) * 512 + h * 64 + k4);
            float4 hv, lv;
            tf32_split(vv.x, hv.x, lv.x);
            tf32_split(vv.y, hv.y, lv.y);
            tf32_split(vv.z, hv.z, lv.z);
            tf32_split(vv.w, hv.w, lv.w);
            *(float4*)&KVh[m * VP + k4] = hv;
            *(float4*)&KVl[m * VP + k4] = lv;
        }
        __syncthreads();
#pragma unroll
        for (int ks = 0; ks < 2; ks++) {
            int kl = wid * 16 + ks * 8;      // local V row base
            int kg = vt * 128 + kl;          // global column in sc
            float ah2[2][4], al2[2][4];
#pragma unroll
            for (int mf = 0; mf < 2; mf++) {
                int r0 = (mf * 16 + qr) * SCP;
                int r1 = (mf * 16 + qr + 8) * SCP;
                tf32_split(sc[r0 + kg + qc],     ah2[mf][0], al2[mf][0]);
                tf32_split(sc[r1 + kg + qc],     ah2[mf][1], al2[mf][1]);
                tf32_split(sc[r0 + kg + qc + 4], ah2[mf][2], al2[mf][2]);
                tf32_split(sc[r1 + kg + qc + 4], ah2[mf][3], al2[mf][3]);
            }
#pragma unroll
            for (int nf = 0; nf < 8; nf++) {
                float bh2[2], bl2[2];
                bh2[0] = KVh[(kl + qc) * VP + nf * 8 + qr];
                bh2[1] = KVh[(kl + qc + 4) * VP + nf * 8 + qr];
                bl2[0] = KVl[(kl + qc) * VP + nf * 8 + qr];
                bl2[1] = KVl[(kl + qc + 4) * VP + nf * 8 + qr];
#pragma unroll
                for (int mf = 0; mf < 2; mf++) {
                    mma8(acc[mf][nf], ah2[mf], bh2);
                    mma8(acc[mf][nf], ah2[mf], bl2);
                    mma8(acc[mf][nf], al2[mf], bh2);
                }
            }
        }
    }
    __syncthreads();

    // ---- cross-warp reduction of partial att (reuse Q/KV smem region) ----
    float* part = sm;    // 8 * 2048 = 16384 floats <= 22784 available
#pragma unroll
    for (int mf = 0; mf < 2; mf++)
#pragma unroll
        for (int nf = 0; nf < 8; nf++) {
            int row0 = mf * 16 + qr;
            int col = nf * 8 + 2 * qc;
            part[wid * 2048 + row0 * 64 + col]           = acc[mf][nf][0];
            part[wid * 2048 + row0 * 64 + col + 1]       = acc[mf][nf][1];
            part[wid * 2048 + (row0 + 8) * 64 + col]     = acc[mf][nf][2];
            part[wid * 2048 + (row0 + 8) * 64 + col + 1] = acc[mf][nf][3];
        }
    __syncthreads();
#pragma unroll
    for (int u = 0; u < 8; u++) {
        int idx = tid + u * 256;        // 0..2047
        float s = 0.f;
#pragma unroll
        for (int w = 0; w < 8; w++) s += part[w * 2048 + idx];
        int row = idx >> 6, col = idx & 63;
        att[(size_t)(b * N_ + n0 + row) * 512 + h * 64 + col] = s;
    }
}

// ---------------- launch ----------------
extern "C" void kernel_launch(void* const* d_in, const int* in_sizes, int n_in,
                              void* d_out, int out_size) {
    const float* user_exo = (const float*)d_in[0];
    const float* exo      = (const float*)d_in[1];
    const float* adj      = (const float*)d_in[2];
    const float* Wq       = (const float*)d_in[3];
    const float* bq       = (const float*)d_in[4];
    const float* Wk       = (const float*)d_in[5];
    const float* bk       = (const float*)d_in[6];
    const float* Wv       = (const float*)d_in[7];
    const float* bv       = (const float*)d_in[8];
    const float* gamma    = (const float*)d_in[9];
    const float* beta     = (const float*)d_in[10];

    float* att  = (float*)d_out;                       // [B, N, DV]
    float* dist = att + (size_t)B_ * N_ * D_;          // [B, NH, N, N]

    const int gemm_smem = 4 * 128 * GP * (int)sizeof(float);                    // 73728
    const int attn_smem = (2 * 32 * QP + 2 * 128 * VP + 32 * SCP) * (int)sizeof(float); // 223744
    cudaFuncSetAttribute(gemm_qkv_tc, cudaFuncAttributeMaxDynamicSharedMemorySize, gemm_smem);
    cudaFuncSetAttribute(attn_tc, cudaFuncAttributeMaxDynamicSharedMemorySize, attn_smem);

    ln_kernel<<<M_, 256>>>(user_exo, gamma, beta);
    gemm_qkv_tc<<<dim3(4, 32, 3), 256, gemm_smem>>>(exo, Wq, bq, Wk, bk, Wv, bv);
    attn_tc<<<dim3(N_ / 32, NH_, B_), 256, attn_smem>>>(adj, att, dist);
}

// round 5
// speedup vs baseline: 1.9908x; 1.3176x over previous
#include <cuda_runtime.h>
#include <cuda_fp16.h>
#include <math.h>
#include <stdint.h>

// Problem dims
#define B_   4
#define N_   1024
#define D_   512
#define NH_  8
#define M_   (B_ * N_)   // 4096 rows

#define SCALE_ 0.04419417382415922f   // 1/sqrt(512)

// ---------------- device scratch (no allocations allowed) ----------------
__device__ float g_c[M_ * D_];   // layernorm output
__device__ float g_q[M_ * D_];
__device__ float g_k[M_ * D_];
__device__ float g_v[M_ * D_];

// ---------------- fp16 split helpers ----------------
// split (x,y) into hi half2 word + lo half2 word;  x = hi + lo + O(2^-22 x)
__device__ __forceinline__ void h2split(float x, float y, uint32_t& h, uint32_t& l) {
    half2 hh = __floats2half2_rn(x, y);
    float2 hf = __half22float2(hh);
    half2 ll = __floats2half2_rn(x - hf.x, y - hf.y);
    h = *(uint32_t*)&hh;
    l = *(uint32_t*)&ll;
}

__device__ __forceinline__ void mma16(float* d, const uint32_t* a, const uint32_t* b) {
    asm volatile("mma.sync.aligned.m16n8k16.row.col.f32.f16.f16.f32 "
        "{%0,%1,%2,%3},{%4,%5,%6,%7},{%8,%9},{%0,%1,%2,%3};"
        : "+f"(d[0]), "+f"(d[1]), "+f"(d[2]), "+f"(d[3])
        : "r"(a[0]), "r"(a[1]), "r"(a[2]), "r"(a[3]), "r"(b[0]), "r"(b[1]));
}

// ---------------- LayerNorm: one block per row ----------------
__global__ void __launch_bounds__(256) ln_kernel(const float* __restrict__ x,
                                                 const float* __restrict__ gamma,
                                                 const float* __restrict__ beta) {
    int row = blockIdx.x;
    int t = threadIdx.x;
    const float* xr = x + (size_t)row * D_;
    float v0 = xr[t], v1 = xr[t + 256];
    float s = v0 + v1;
    float sq = v0 * v0 + v1 * v1;
#pragma unroll
    for (int o = 16; o; o >>= 1) {
        s  += __shfl_xor_sync(0xffffffffu, s,  o);
        sq += __shfl_xor_sync(0xffffffffu, sq, o);
    }
    __shared__ float shs[8], shq[8];
    if ((t & 31) == 0) { shs[t >> 5] = s; shq[t >> 5] = sq; }
    __syncthreads();
    s = 0.f; sq = 0.f;
#pragma unroll
    for (int i = 0; i < 8; i++) { s += shs[i]; sq += shq[i]; }
    float mean = s * (1.0f / 512.0f);
    float var  = sq * (1.0f / 512.0f) - mean * mean;
    float rstd = rsqrtf(var + 1e-5f);
    float* o = g_c + (size_t)row * D_;
    o[t]       = (v0 - mean) * rstd * gamma[t]       + beta[t];
    o[t + 256] = (v1 - mean) * rstd * gamma[t + 256] + beta[t + 256];
}

// ---------------- QKV GEMM via split-fp16 mma (3x) ----------------
// out = A @ W^T + bias.  z: 0->q(c,Wq), 1->k(c,Wk), 2->v(exo,Wv)
// 128x128 block tile, BK=64 floats, 8 warps (warp tile 64x32).
// smem rows: 32 half2 words (=64 halves) padded to 36 -> frag loads conflict-free.
#define GST 36
__global__ void __launch_bounds__(256) gemm_qkv_tc(
    const float* __restrict__ exo,
    const float* __restrict__ Wq, const float* __restrict__ bq,
    const float* __restrict__ Wk, const float* __restrict__ bk,
    const float* __restrict__ Wv, const float* __restrict__ bv) {

    extern __shared__ uint32_t sg[];
    uint32_t* Ah = sg;                 // 128*36 words
    uint32_t* Al = Ah + 128 * GST;
    uint32_t* Bh = Al + 128 * GST;
    uint32_t* Bl = Bh + 128 * GST;

    const float* A; const float* W; const float* bias; float* O;
    int z = blockIdx.z;
    if (z == 0)      { A = g_c; W = Wq; bias = bq; O = g_q; }
    else if (z == 1) { A = g_c; W = Wk; bias = bk; O = g_k; }
    else             { A = exo; W = Wv; bias = bv; O = g_v; }

    int tid = threadIdx.x;
    int lane = tid & 31, wid = tid >> 5;
    int wm = (wid & 1) * 64, wn = (wid >> 1) * 32;
    int qr = lane >> 2, qc = lane & 3;
    int bm = blockIdx.y * 128, bn = blockIdx.x * 128;

    float C[4][4][4] = {};

    for (int k0 = 0; k0 < 512; k0 += 64) {
        __syncthreads();
#pragma unroll
        for (int u = 0; u < 8; u++) {
            int idx = tid + u * 256;
            int r = idx >> 4;
            int c4 = (idx & 15) * 4;
            int o = r * GST + (c4 >> 1);
            float4 av = *(const float4*)(A + (size_t)(bm + r) * 512 + k0 + c4);
            uint32_t h0, l0, h1, l1;
            h2split(av.x, av.y, h0, l0);
            h2split(av.z, av.w, h1, l1);
            *(uint2*)&Ah[o] = make_uint2(h0, h1);
            *(uint2*)&Al[o] = make_uint2(l0, l1);
            float4 wv = *(const float4*)(W + (size_t)(bn + r) * 512 + k0 + c4);
            h2split(wv.x, wv.y, h0, l0);
            h2split(wv.z, wv.w, h1, l1);
            *(uint2*)&Bh[o] = make_uint2(h0, h1);
            *(uint2*)&Bl[o] = make_uint2(l0, l1);
        }
        __syncthreads();
#pragma unroll
        for (int ks = 0; ks < 4; ks++) {
            int kb = ks * 8;              // half2-word offset of this k16 chunk
            uint32_t ah[4][4], al[4][4];
#pragma unroll
            for (int mf = 0; mf < 4; mf++) {
                int r = wm + mf * 16;
                ah[mf][0] = Ah[(r + qr) * GST + kb + qc];
                ah[mf][1] = Ah[(r + qr + 8) * GST + kb + qc];
                ah[mf][2] = Ah[(r + qr) * GST + kb + 4 + qc];
                ah[mf][3] = Ah[(r + qr + 8) * GST + kb + 4 + qc];
                al[mf][0] = Al[(r + qr) * GST + kb + qc];
                al[mf][1] = Al[(r + qr + 8) * GST + kb + qc];
                al[mf][2] = Al[(r + qr) * GST + kb + 4 + qc];
                al[mf][3] = Al[(r + qr + 8) * GST + kb + 4 + qc];
            }
            uint32_t bh[4][2], bl[4][2];
#pragma unroll
            for (int nf = 0; nf < 4; nf++) {
                int n = wn + nf * 8;
                bh[nf][0] = Bh[(n + qr) * GST + kb + qc];
                bh[nf][1] = Bh[(n + qr) * GST + kb + 4 + qc];
                bl[nf][0] = Bl[(n + qr) * GST + kb + qc];
                bl[nf][1] = Bl[(n + qr) * GST + kb + 4 + qc];
            }
#pragma unroll
            for (int mf = 0; mf < 4; mf++)
#pragma unroll
                for (int nf = 0; nf < 4; nf++) {
                    mma16(C[mf][nf], ah[mf], bh[nf]);
                    mma16(C[mf][nf], ah[mf], bl[nf]);
                    mma16(C[mf][nf], al[mf], bh[nf]);
                }
        }
    }
#pragma unroll
    for (int mf = 0; mf < 4; mf++)
#pragma unroll
        for (int nf = 0; nf < 4; nf++) {
            int row = bm + wm + mf * 16 + qr;
            int col = bn + wn + nf * 8 + 2 * qc;
            float2 bv2 = *(const float2*)(bias + col);
            float2 o0 = make_float2(C[mf][nf][0] + bv2.x, C[mf][nf][1] + bv2.y);
            float2 o1 = make_float2(C[mf][nf][2] + bv2.x, C[mf][nf][3] + bv2.y);
            *(float2*)(O + (size_t)row * 512 + col) = o0;
            *(float2*)(O + (size_t)(row + 8) * 512 + col) = o1;
        }
}

// ---------------- attention via split-fp16 mma ----------------
// one block per (b, h, 32-row q tile); 8 warps.
#define QST 36     // Q row stride (half2 words)
#define KST 36     // K row stride (half2 words)
#define VST 69     // V^T row stride (half2 words along m)
#define SCP 1036   // score row stride (floats)
__global__ void __launch_bounds__(256) attn_tc(const float* __restrict__ adj,
                                               float* __restrict__ att,
                                               float* __restrict__ dist) {
    extern __shared__ uint32_t su[];
    uint32_t* Qh = su;                  // 32*36  = 1152 words
    uint32_t* Ql = Qh + 32 * QST;       // 1152
    uint32_t* Kh = Ql + 32 * QST;       // 4608 (reused as V^T hi: 64*69=4416)
    uint32_t* Kl = Kh + 128 * KST;      // 4608 (reused as V^T lo)
    float* sc = (float*)(Kl + 128 * KST);  // 32*1036 floats

    int qt = blockIdx.x, h = blockIdx.y, b = blockIdx.z;
    int n0 = qt * 32;
    int tid = threadIdx.x;
    int lane = tid & 31, wid = tid >> 5;
    int qr = lane >> 2, qc = lane & 3;

    // ---- stage Q (pre-scaled) hi/lo ----
#pragma unroll
    for (int u = 0; u < 2; u++) {
        int idx = tid + u * 256;        // f4 units 0..511
        int m = idx >> 4;               // 0..31
        int c4 = (idx & 15) * 4;
        float4 qv = *(const float4*)(g_q + (size_t)(b * N_ + n0 + m) * 512 + h * 64 + c4);
        uint32_t h0, l0, h1, l1;
        h2split(qv.x * SCALE_, qv.y * SCALE_, h0, l0);
        h2split(qv.z * SCALE_, qv.w * SCALE_, h1, l1);
        int o = m * QST + (c4 >> 1);
        *(uint2*)&Qh[o] = make_uint2(h0, h1);
        *(uint2*)&Ql[o] = make_uint2(l0, l1);
    }
    __syncthreads();

    // ---- preload Q hi/lo fragments into registers ----
    uint32_t qh[2][4][4], ql[2][4][4];
#pragma unroll
    for (int mf = 0; mf < 2; mf++)
#pragma unroll
        for (int ks = 0; ks < 4; ks++) {
            int r = mf * 16, kb = ks * 8;
            qh[mf][ks][0] = Qh[(r + qr) * QST + kb + qc];
            qh[mf][ks][1] = Qh[(r + qr + 8) * QST + kb + qc];
            qh[mf][ks][2] = Qh[(r + qr) * QST + kb + 4 + qc];
            qh[mf][ks][3] = Qh[(r + qr + 8) * QST + kb + 4 + qc];
            ql[mf][ks][0] = Ql[(r + qr) * QST + kb + qc];
            ql[mf][ks][1] = Ql[(r + qr + 8) * QST + kb + qc];
            ql[mf][ks][2] = Ql[(r + qr) * QST + kb + 4 + qc];
            ql[mf][ks][3] = Ql[(r + qr + 8) * QST + kb + 4 + qc];
        }

    // ---- phase 1: scores S[32,1024] = Qs . K^T ----
    for (int kt = 0; kt < 8; kt++) {
        __syncthreads();
#pragma unroll
        for (int u = 0; u < 8; u++) {
            int idx = tid + u * 256;    // f4 units 0..2047
            int n = idx >> 4;           // 0..127
            int c4 = (idx & 15) * 4;
            float4 kv = *(const float4*)(g_k + (size_t)(b * N_ + kt * 128 + n) * 512 + h * 64 + c4);
            uint32_t h0, l0, h1, l1;
            h2split(kv.x, kv.y, h0, l0);
            h2split(kv.z, kv.w, h1, l1);
            int o = n * KST + (c4 >> 1);
            *(uint2*)&Kh[o] = make_uint2(h0, h1);
            *(uint2*)&Kl[o] = make_uint2(l0, l1);
        }
        __syncthreads();
        float C[2][2][4] = {};
#pragma unroll
        for (int ks = 0; ks < 4; ks++) {
            int kb = ks * 8;
            uint32_t bh[2][2], bl[2][2];
#pragma unroll
            for (int nf = 0; nf < 2; nf++) {
                int n = wid * 16 + nf * 8;
                bh[nf][0] = Kh[(n + qr) * KST + kb + qc];
                bh[nf][1] = Kh[(n + qr) * KST + kb + 4 + qc];
                bl[nf][0] = Kl[(n + qr) * KST + kb + qc];
                bl[nf][1] = Kl[(n + qr) * KST + kb + 4 + qc];
            }
#pragma unroll
            for (int mf = 0; mf < 2; mf++)
#pragma unroll
                for (int nf = 0; nf < 2; nf++) {
                    mma16(C[mf][nf], qh[mf][ks], bh[nf]);
                    mma16(C[mf][nf], qh[mf][ks], bl[nf]);
                    mma16(C[mf][nf], ql[mf][ks], bh[nf]);
                }
        }
#pragma unroll
        for (int mf = 0; mf < 2; mf++)
#pragma unroll
            for (int nf = 0; nf < 2; nf++) {
                int row = mf * 16 + qr;
                int colg = kt * 128 + wid * 16 + nf * 8 + 2 * qc;
                *(float2*)&sc[row * SCP + colg]       = make_float2(C[mf][nf][0], C[mf][nf][1]);
                *(float2*)&sc[(row + 8) * SCP + colg] = make_float2(C[mf][nf][2], C[mf][nf][3]);
            }
    }
    __syncthreads();

    // ---- softmax + adj mask + dist write (warp wid: rows wid + 8*rr) ----
    float* distb = dist + (size_t)(b * NH_ + h) * N_ * N_;
#pragma unroll
    for (int rr = 0; rr < 4; rr++) {
        int r = wid + rr * 8;
        float* srow = sc + r * SCP;
        float mx = -3.402823466e38f;
        for (int c = lane; c < 1024; c += 32) mx = fmaxf(mx, srow[c]);
#pragma unroll
        for (int o = 16; o; o >>= 1) mx = fmaxf(mx, __shfl_xor_sync(0xffffffffu, mx, o));
        float s = 0.f;
        for (int c = lane; c < 1024; c += 32) {
            float e = __expf(srow[c] - mx);
            srow[c] = e;
            s += e;
        }
#pragma unroll
        for (int o = 16; o; o >>= 1) s += __shfl_xor_sync(0xffffffffu, s, o);
        float inv = 1.0f / s;
        const float* arow = adj + (size_t)(n0 + r) * 1024;
        float* drow = distb + (size_t)(n0 + r) * 1024;
        for (int c = lane; c < 1024; c += 32) {
            float p = srow[c] * inv * arow[c];
            srow[c] = p;       // keep masked dist in smem for P.V
            drow[c] = p;       // coalesced dist output
        }
    }

    // ---- phase 3: att[32,64] = P . V  (warp wid owns 16 k-rows of each tile) ----
    uint32_t* Vh = Kh;   // reuse K staging region: V^T hi [64 d rows][69 m-half2]
    uint32_t* Vl = Kl;
    float acc[2][8][4] = {};
    for (int vt = 0; vt < 8; vt++) {
        __syncthreads();   // first iter: softmax done; later: prev mma done
#pragma unroll
        for (int u = 0; u < 8; u++) {
            int idx = tid + u * 256;    // 2048 slots
            int m2 = idx >> 5;          // 0..63  (m pair)
            int d2 = idx & 31;          // 0..31  (d pair)
            const float* vp = g_v + (size_t)(b * N_ + vt * 128 + 2 * m2) * 512 + h * 64 + 2 * d2;
            float2 v0 = *(const float2*)vp;          // row m=2*m2
            float2 v1 = *(const float2*)(vp + 512);  // row m=2*m2+1
            uint32_t h0, l0, h1, l1;
            h2split(v0.x, v1.x, h0, l0);   // d = 2*d2, packed (m, m+1)
            h2split(v0.y, v1.y, h1, l1);   // d = 2*d2+1
            Vh[(2 * d2) * VST + m2] = h0;
            Vl[(2 * d2) * VST + m2] = l0;
            Vh[(2 * d2 + 1) * VST + m2] = h1;
            Vl[(2 * d2 + 1) * VST + m2] = l1;
        }
        __syncthreads();
        int kg = vt * 128 + wid * 16;
        uint32_t ah[2][4], alo[2][4];
#pragma unroll
        for (int mf = 0; mf < 2; mf++) {
            int r0 = (mf * 16 + qr) * SCP + kg;
            int r1 = (mf * 16 + qr + 8) * SCP + kg;
            float2 s0 = *(const float2*)&sc[r0 + 2 * qc];
            float2 s1 = *(const float2*)&sc[r1 + 2 * qc];
            float2 s2 = *(const float2*)&sc[r0 + 2 * qc + 8];
            float2 s3 = *(const float2*)&sc[r1 + 2 * qc + 8];
            h2split(s0.x, s0.y, ah[mf][0], alo[mf][0]);
            h2split(s1.x, s1.y, ah[mf][1], alo[mf][1]);
            h2split(s2.x, s2.y, ah[mf][2], alo[mf][2]);
            h2split(s3.x, s3.y, ah[mf][3], alo[mf][3]);
        }
#pragma unroll
        for (int nf = 0; nf < 8; nf++) {
            int rn = (nf * 8 + qr) * VST + wid * 8 + qc;
            uint32_t bh[2], bl[2];
            bh[0] = Vh[rn];     bh[1] = Vh[rn + 4];
            bl[0] = Vl[rn];     bl[1] = Vl[rn + 4];
#pragma unroll
            for (int mf = 0; mf < 2; mf++) {
                mma16(acc[mf][nf], ah[mf], bh);
                mma16(acc[mf][nf], ah[mf], bl);
                mma16(acc[mf][nf], alo[mf], bh);
            }
        }
    }
    __syncthreads();

    // ---- cross-warp reduction of partial att (overlaps all earlier smem) ----
    float* part = (float*)su;    // 8 * 2048 = 16384 floats, all prior data dead
#pragma unroll
    for (int mf = 0; mf < 2; mf++)
#pragma unroll
        for (int nf = 0; nf < 8; nf++) {
            int row0 = mf * 16 + qr;
            int col = nf * 8 + 2 * qc;
            part[wid * 2048 + row0 * 64 + col]           = acc[mf][nf][0];
            part[wid * 2048 + row0 * 64 + col + 1]       = acc[mf][nf][1];
            part[wid * 2048 + (row0 + 8) * 64 + col]     = acc[mf][nf][2];
            part[wid * 2048 + (row0 + 8) * 64 + col + 1] = acc[mf][nf][3];
        }
    __syncthreads();
#pragma unroll
    for (int u = 0; u < 8; u++) {
        int idx = tid + u * 256;        // 0..2047
        float s = 0.f;
#pragma unroll
        for (int w = 0; w < 8; w++) s += part[w * 2048 + idx];
        int row = idx >> 6, col = idx & 63;
        att[(size_t)(b * N_ + n0 + row) * 512 + h * 64 + col] = s;
    }
}

// ---------------- launch ----------------
extern "C" void kernel_launch(void* const* d_in, const int* in_sizes, int n_in,
                              void* d_out, int out_size) {
    const float* user_exo = (const float*)d_in[0];
    const float* exo      = (const float*)d_in[1];
    const float* adj      = (const float*)d_in[2];
    const float* Wq       = (const float*)d_in[3];
    const float* bq       = (const float*)d_in[4];
    const float* Wk       = (const float*)d_in[5];
    const float* bk       = (const float*)d_in[6];
    const float* Wv       = (const float*)d_in[7];
    const float* bv       = (const float*)d_in[8];
    const float* gamma    = (const float*)d_in[9];
    const float* beta     = (const float*)d_in[10];

    float* att  = (float*)d_out;                       // [B, N, DV]
    float* dist = att + (size_t)B_ * N_ * D_;          // [B, NH, N, N]

    const int gemm_smem = 4 * 128 * GST * (int)sizeof(uint32_t);   // 73728
    const int attn_smem = (2 * 32 * QST + 2 * 128 * KST) * (int)sizeof(uint32_t)
                        + 32 * SCP * (int)sizeof(float);           // 178688
    cudaFuncSetAttribute(gemm_qkv_tc, cudaFuncAttributeMaxDynamicSharedMemorySize, gemm_smem);
    cudaFuncSetAttribute(attn_tc, cudaFuncAttributeMaxDynamicSharedMemorySize, attn_smem);

    ln_kernel<<<M_, 256>>>(user_exo, gamma, beta);
    gemm_qkv_tc<<<dim3(4, 32, 3), 256, gemm_smem>>>(exo, Wq, bq, Wk, bk, Wv, bv);
    attn_tc<<<dim3(N_ / 32, NH_, B_), 256, attn_smem>>>(adj, att, dist);
}

// round 6
// speedup vs baseline: 2.2047x; 1.1074x over previous
#include <cuda_runtime.h>
#include <cuda_fp16.h>
#include <math.h>
#include <stdint.h>

// Problem dims
#define B_   4
#define N_   1024
#define D_   512
#define NH_  8
#define M_   (B_ * N_)   // 4096 rows
#define WPR  256         // packed half2 words per row (D_/2)

#define SCALE_ 0.04419417382415922f   // 1/sqrt(512)

// ---------------- device scratch (packed fp16 hi/lo streams) ----------------
__device__ uint32_t g_ch[M_ * WPR], g_cl[M_ * WPR];   // layernorm(c)
__device__ uint32_t g_eh[M_ * WPR], g_el[M_ * WPR];   // exo
__device__ uint32_t g_wh[3][512 * WPR], g_wl[3][512 * WPR];
__device__ uint32_t g_qh[M_ * WPR], g_ql[M_ * WPR];   // scaled q
__device__ uint32_t g_kh[M_ * WPR], g_kl[M_ * WPR];
__device__ uint32_t g_vh[M_ * WPR], g_vl[M_ * WPR];   // m-major (d,d+1) pairs
__device__ uint32_t g_vth[32 * 64 * 512], g_vtl[32 * 64 * 512]; // [bh][d][m2] (m,m+1) pairs

// ---------------- helpers ----------------
__device__ __forceinline__ void h2split(float x, float y, uint32_t& h, uint32_t& l) {
    half2 hh = __floats2half2_rn(x, y);
    float2 hf = __half22float2(hh);
    half2 ll = __floats2half2_rn(x - hf.x, y - hf.y);
    h = *(uint32_t*)&hh;
    l = *(uint32_t*)&ll;
}

__device__ __forceinline__ void mma16(float* d, const uint32_t* a, const uint32_t* b) {
    asm volatile("mma.sync.aligned.m16n8k16.row.col.f32.f16.f16.f32 "
        "{%0,%1,%2,%3},{%4,%5,%6,%7},{%8,%9},{%0,%1,%2,%3};"
        : "+f"(d[0]), "+f"(d[1]), "+f"(d[2]), "+f"(d[3])
        : "r"(a[0]), "r"(a[1]), "r"(a[2]), "r"(a[3]), "r"(b[0]), "r"(b[1]));
}

__device__ __forceinline__ void cpa16(uint32_t dst, const void* src) {
    asm volatile("cp.async.cg.shared.global [%0], [%1], 16;" :: "r"(dst), "l"(src));
}
#define CPC() asm volatile("cp.async.commit_group;")
#define CPW(n) asm volatile("cp.async.wait_group %0;" :: "n"(n))

// ---------------- LayerNorm + exo convert: one block per row ----------------
__global__ void __launch_bounds__(256) ln_prep(const float* __restrict__ x,
                                               const float* __restrict__ exo,
                                               const float* __restrict__ gamma,
                                               const float* __restrict__ beta) {
    int row = blockIdx.x;
    int t = threadIdx.x;
    float2 xv = *(const float2*)(x + (size_t)row * D_ + 2 * t);
    float s = xv.x + xv.y;
    float sq = xv.x * xv.x + xv.y * xv.y;
#pragma unroll
    for (int o = 16; o; o >>= 1) {
        s  += __shfl_xor_sync(0xffffffffu, s,  o);
        sq += __shfl_xor_sync(0xffffffffu, sq, o);
    }
    __shared__ float shs[8], shq[8];
    if ((t & 31) == 0) { shs[t >> 5] = s; shq[t >> 5] = sq; }
    __syncthreads();
    s = 0.f; sq = 0.f;
#pragma unroll
    for (int i = 0; i < 8; i++) { s += shs[i]; sq += shq[i]; }
    float mean = s * (1.0f / 512.0f);
    float var  = sq * (1.0f / 512.0f) - mean * mean;
    float rstd = rsqrtf(var + 1e-5f);
    float2 gv = *(const float2*)(gamma + 2 * t);
    float2 bv = *(const float2*)(beta + 2 * t);
    float c0 = (xv.x - mean) * rstd * gv.x + bv.x;
    float c1 = (xv.y - mean) * rstd * gv.y + bv.y;
    uint32_t h, l;
    h2split(c0, c1, h, l);
    g_ch[(size_t)row * WPR + t] = h;
    g_cl[(size_t)row * WPR + t] = l;
    float2 ev = *(const float2*)(exo + (size_t)row * D_ + 2 * t);
    h2split(ev.x, ev.y, h, l);
    g_eh[(size_t)row * WPR + t] = h;
    g_el[(size_t)row * WPR + t] = l;
}

// ---------------- W convert ----------------
__global__ void __launch_bounds__(256) w_cvt(const float* __restrict__ Wq,
                                             const float* __restrict__ Wk,
                                             const float* __restrict__ Wv) {
    int row = blockIdx.x, z = blockIdx.y, t = threadIdx.x;
    const float* W = (z == 0) ? Wq : (z == 1) ? Wk : Wv;
    float2 w = *(const float2*)(W + (size_t)row * 512 + 2 * t);
    uint32_t h, l;
    h2split(w.x, w.y, h, l);
    g_wh[z][row * WPR + t] = h;
    g_wl[z][row * WPR + t] = l;
}

// ---------------- QKV GEMM (packed-in, packed-out) ----------------
#define GST 36
__global__ void __launch_bounds__(256) gemm_qkv_tc(
    const float* __restrict__ bq, const float* __restrict__ bk,
    const float* __restrict__ bv) {

    extern __shared__ uint32_t sg[];
    uint32_t* Ah = sg;
    uint32_t* Al = Ah + 128 * GST;
    uint32_t* Bh = Al + 128 * GST;
    uint32_t* Bl = Bh + 128 * GST;
    uint32_t aAh = (uint32_t)__cvta_generic_to_shared(Ah);
    uint32_t aAl = (uint32_t)__cvta_generic_to_shared(Al);
    uint32_t aBh = (uint32_t)__cvta_generic_to_shared(Bh);
    uint32_t aBl = (uint32_t)__cvta_generic_to_shared(Bl);

    int z = blockIdx.z;
    const uint32_t* Asrc_h = (z == 2) ? g_eh : g_ch;
    const uint32_t* Asrc_l = (z == 2) ? g_el : g_cl;
    const uint32_t* Bsrc_h = g_wh[z];
    const uint32_t* Bsrc_l = g_wl[z];
    const float* bias = (z == 0) ? bq : (z == 1) ? bk : bv;
    uint32_t* Oh = (z == 0) ? g_qh : (z == 1) ? g_kh : g_vh;
    uint32_t* Ol = (z == 0) ? g_ql : (z == 1) ? g_kl : g_vl;
    float scl = (z == 0) ? SCALE_ : 1.0f;

    int tid = threadIdx.x;
    int lane = tid & 31, wid = tid >> 5;
    int wm = (wid & 1) * 64, wn = (wid >> 1) * 32;
    int qr = lane >> 2, qc = lane & 3;
    int bm = blockIdx.y * 128, bn = blockIdx.x * 128;

    float C[4][4][4] = {};

    int sr = tid >> 3;            // 0..31
    int scc = (tid & 7) * 4;      // word chunk 0,4..28

    for (int k0 = 0; k0 < WPR; k0 += 32) {
        __syncthreads();
#pragma unroll
        for (int u = 0; u < 4; u++) {
            int r = sr + u * 32;
            int soff = (r * GST + scc) * 4;
            cpa16(aAh + soff, Asrc_h + (size_t)(bm + r) * WPR + k0 + scc);
            cpa16(aAl + soff, Asrc_l + (size_t)(bm + r) * WPR + k0 + scc);
            cpa16(aBh + soff, Bsrc_h + (size_t)(bn + r) * WPR + k0 + scc);
            cpa16(aBl + soff, Bsrc_l + (size_t)(bn + r) * WPR + k0 + scc);
        }
        CPC(); CPW(0);
        __syncthreads();
#pragma unroll
        for (int ks = 0; ks < 4; ks++) {
            int kb = ks * 8;
            uint32_t ah[4][4], al[4][4];
#pragma unroll
            for (int mf = 0; mf < 4; mf++) {
                int r = wm + mf * 16;
                ah[mf][0] = Ah[(r + qr) * GST + kb + qc];
                ah[mf][1] = Ah[(r + qr + 8) * GST + kb + qc];
                ah[mf][2] = Ah[(r + qr) * GST + kb + 4 + qc];
                ah[mf][3] = Ah[(r + qr + 8) * GST + kb + 4 + qc];
                al[mf][0] = Al[(r + qr) * GST + kb + qc];
                al[mf][1] = Al[(r + qr + 8) * GST + kb + qc];
                al[mf][2] = Al[(r + qr) * GST + kb + 4 + qc];
                al[mf][3] = Al[(r + qr + 8) * GST + kb + 4 + qc];
            }
            uint32_t bh[4][2], bl[4][2];
#pragma unroll
            for (int nf = 0; nf < 4; nf++) {
                int n = wn + nf * 8;
                bh[nf][0] = Bh[(n + qr) * GST + kb + qc];
                bh[nf][1] = Bh[(n + qr) * GST + kb + 4 + qc];
                bl[nf][0] = Bl[(n + qr) * GST + kb + qc];
                bl[nf][1] = Bl[(n + qr) * GST + kb + 4 + qc];
            }
#pragma unroll
            for (int mf = 0; mf < 4; mf++)
#pragma unroll
                for (int nf = 0; nf < 4; nf++) {
                    mma16(C[mf][nf], ah[mf], bh[nf]);
                    mma16(C[mf][nf], ah[mf], bl[nf]);
                    mma16(C[mf][nf], al[mf], bh[nf]);
                }
        }
    }
    // epilogue: add bias, scale, split, pack
#pragma unroll
    for (int mf = 0; mf < 4; mf++)
#pragma unroll
        for (int nf = 0; nf < 4; nf++) {
            int r0 = bm + wm + mf * 16 + qr;
            int col = bn + wn + nf * 8 + 2 * qc;
            int w = col >> 1;
            float2 bb = *(const float2*)(bias + col);
            uint32_t h, l;
            h2split((C[mf][nf][0] + bb.x) * scl, (C[mf][nf][1] + bb.y) * scl, h, l);
            Oh[(size_t)r0 * WPR + w] = h;
            Ol[(size_t)r0 * WPR + w] = l;
            h2split((C[mf][nf][2] + bb.x) * scl, (C[mf][nf][3] + bb.y) * scl, h, l);
            Oh[(size_t)(r0 + 8) * WPR + w] = h;
            Ol[(size_t)(r0 + 8) * WPR + w] = l;
        }
}

// ---------------- V transpose-repack: [m][(d,d+1)] -> [bh][d][(m,m+1)] ----------------
__global__ void __launch_bounds__(256) convert_v() {
    int mc = blockIdx.x;          // 0..7 (128-m chunk)
    int bh = blockIdx.y;          // 0..31
    int b = bh >> 3, h = bh & 7;
    int tid = threadIdx.x;
    __shared__ uint32_t sh[128 * 33], sl[128 * 33];
#pragma unroll
    for (int u = 0; u < 16; u++) {
        int idx = tid + u * 256;
        int m = idx >> 5, d2 = idx & 31;
        size_t src = (size_t)(b * 1024 + mc * 128 + m) * WPR + h * 32 + d2;
        sh[m * 33 + d2] = g_vh[src];
        sl[m * 33 + d2] = g_vl[src];
    }
    __syncthreads();
#pragma unroll
    for (int u = 0; u < 16; u++) {
        int idx = tid + u * 256;
        int d = idx >> 6, m2 = idx & 63;
        int d2 = d >> 1;
        uint32_t sel = (d & 1) ? 0x7632u : 0x5410u;
        uint32_t a0 = sh[(2 * m2) * 33 + d2], a1 = sh[(2 * m2 + 1) * 33 + d2];
        size_t dst = ((size_t)bh * 64 + d) * 512 + mc * 64 + m2;
        g_vth[dst] = __byte_perm(a0, a1, sel);
        a0 = sl[(2 * m2) * 33 + d2]; a1 = sl[(2 * m2 + 1) * 33 + d2];
        g_vtl[dst] = __byte_perm(a0, a1, sel);
    }
}

// ---------------- attention ----------------
#define QST 36     // Q row stride (words)
#define KST 36     // K row stride (words)
#define VST 68     // V^T row stride (words)
#define SCP 1036   // score row stride (floats)
// smem: Qh/Ql 2*1152 | K double-buffer 2*2*128*36=18432 | sc 32*1036
__global__ void __launch_bounds__(256) attn_tc(const float* __restrict__ adj,
                                               float* __restrict__ att,
                                               float* __restrict__ dist) {
    extern __shared__ uint32_t su[];
    uint32_t* Qh = su;
    uint32_t* Ql = Qh + 32 * QST;
    uint32_t* Kbuf = Ql + 32 * QST;              // 18432 words, also V buffers
    float* sc = (float*)(Kbuf + 2 * 2 * 128 * KST);

    int qt = blockIdx.x, h = blockIdx.y, b = blockIdx.z;
    int bh = b * NH_ + h;
    int n0 = qt * 32;
    int tid = threadIdx.x;
    int lane = tid & 31, wid = tid >> 5;
    int qr = lane >> 2, qc = lane & 3;

    uint32_t* KhB[2] = { Kbuf, Kbuf + 2 * 128 * KST };
    uint32_t* KlB[2] = { Kbuf + 128 * KST, Kbuf + 3 * 128 * KST };
    uint32_t aKh[2], aKl[2];
    aKh[0] = (uint32_t)__cvta_generic_to_shared(KhB[0]);
    aKl[0] = (uint32_t)__cvta_generic_to_shared(KlB[0]);
    aKh[1] = (uint32_t)__cvta_generic_to_shared(KhB[1]);
    aKl[1] = (uint32_t)__cvta_generic_to_shared(KlB[1]);

    // K staging (pure copy, cp.async): tile kt -> buf
    int s_n = tid >> 3;               // 0..31
    int s_cc = (tid & 7) * 4;         // 0..28
    const uint32_t* kh_base = g_kh + (size_t)b * N_ * WPR + h * 32;
    const uint32_t* kl_base = g_kl + (size_t)b * N_ * WPR + h * 32;
#define STAGE_K(kt, bi) do {                                                    \
    const uint32_t* _sh = kh_base + (size_t)((kt) * 128) * WPR;                 \
    const uint32_t* _sl = kl_base + (size_t)((kt) * 128) * WPR;                 \
    _Pragma("unroll")                                                           \
    for (int _u = 0; _u < 4; _u++) {                                            \
        int _n = s_n + _u * 32;                                                 \
        int _so = (_n * KST + s_cc) * 4;                                        \
        cpa16(aKh[bi] + _so, _sh + (size_t)_n * WPR + s_cc);                    \
        cpa16(aKl[bi] + _so, _sl + (size_t)_n * WPR + s_cc);                    \
    } } while (0)

    // V staging: tile vt (128 m) -> [64 d][64 m2 words]
    int v_d = tid >> 2;               // 0..63
    int v_jc = (tid & 3) * 4;         // 0..12
    const uint32_t* vth_base = g_vth + (size_t)bh * 64 * 512;
    const uint32_t* vtl_base = g_vtl + (size_t)bh * 64 * 512;
#define STAGE_V(vt, bi) do {                                                    \
    _Pragma("unroll")                                                           \
    for (int _u = 0; _u < 4; _u++) {                                            \
        int _j = v_jc + _u * 16;                                                \
        int _so = (v_d * VST + _j) * 4;                                         \
        cpa16(aKh[bi] + _so, vth_base + (size_t)v_d * 512 + (vt) * 64 + _j);    \
        cpa16(aKl[bi] + _so, vtl_base + (size_t)v_d * 512 + (vt) * 64 + _j);    \
    } } while (0)

    // kick off K tile 0 while copying Q
    STAGE_K(0, 0); CPC();

    // ---- stage Q (plain copy of packed words) ----
    {
        int m = tid >> 3, cc = (tid & 7) * 4;
        const uint32_t* qsrc_h = g_qh + (size_t)(b * N_ + n0 + m) * WPR + h * 32 + cc;
        const uint32_t* qsrc_l = g_ql + (size_t)(b * N_ + n0 + m) * WPR + h * 32 + cc;
        *(uint4*)&Qh[m * QST + cc] = *(const uint4*)qsrc_h;
        *(uint4*)&Ql[m * QST + cc] = *(const uint4*)qsrc_l;
    }
    __syncthreads();

    // ---- preload Q hi/lo fragments ----
    uint32_t qh[2][4][4], ql[2][4][4];
#pragma unroll
    for (int mf = 0; mf < 2; mf++)
#pragma unroll
        for (int ks = 0; ks < 4; ks++) {
            int r = mf * 16, kb = ks * 8;
            qh[mf][ks][0] = Qh[(r + qr) * QST + kb + qc];
            qh[mf][ks][1] = Qh[(r + qr + 8) * QST + kb + qc];
            qh[mf][ks][2] = Qh[(r + qr) * QST + kb + 4 + qc];
            qh[mf][ks][3] = Qh[(r + qr + 8) * QST + kb + 4 + qc];
            ql[mf][ks][0] = Ql[(r + qr) * QST + kb + qc];
            ql[mf][ks][1] = Ql[(r + qr + 8) * QST + kb + qc];
            ql[mf][ks][2] = Ql[(r + qr) * QST + kb + 4 + qc];
            ql[mf][ks][3] = Ql[(r + qr + 8) * QST + kb + 4 + qc];
        }

    // ---- phase 1: scores, double-buffered K ----
    for (int kt = 0; kt < 8; kt++) {
        if (kt < 7) {
            __syncthreads();                      // buf[(kt+1)&1] free
            STAGE_K(kt + 1, (kt + 1) & 1); CPC(); CPW(1);
        } else {
            CPW(0);
        }
        __syncthreads();
        const uint32_t* Khc = KhB[kt & 1];
        const uint32_t* Klc = KlB[kt & 1];
        float C[2][2][4] = {};
#pragma unroll
        for (int ks = 0; ks < 4; ks++) {
            int kb = ks * 8;
            uint32_t bhf[2][2], blf[2][2];
#pragma unroll
            for (int nf = 0; nf < 2; nf++) {
                int n = wid * 16 + nf * 8;
                bhf[nf][0] = Khc[(n + qr) * KST + kb + qc];
                bhf[nf][1] = Khc[(n + qr) * KST + kb + 4 + qc];
                blf[nf][0] = Klc[(n + qr) * KST + kb + qc];
                blf[nf][1] = Klc[(n + qr) * KST + kb + 4 + qc];
            }
#pragma unroll
            for (int mf = 0; mf < 2; mf++)
#pragma unroll
                for (int nf = 0; nf < 2; nf++) {
                    mma16(C[mf][nf], qh[mf][ks], bhf[nf]);
                    mma16(C[mf][nf], qh[mf][ks], blf[nf]);
                    mma16(C[mf][nf], ql[mf][ks], bhf[nf]);
                }
        }
#pragma unroll
        for (int mf = 0; mf < 2; mf++)
#pragma unroll
            for (int nf = 0; nf < 2; nf++) {
                int row = mf * 16 + qr;
                int colg = kt * 128 + wid * 16 + nf * 8 + 2 * qc;
                *(float2*)&sc[row * SCP + colg]       = make_float2(C[mf][nf][0], C[mf][nf][1]);
                *(float2*)&sc[(row + 8) * SCP + colg] = make_float2(C[mf][nf][2], C[mf][nf][3]);
            }
    }
    __syncthreads();   // sc complete; K buffers free

    // prefetch V tile 0 (overlaps softmax)
    STAGE_V(0, 0); CPC();

    // ---- softmax + adj mask + dist write (warp wid: rows wid + 8*rr) ----
    float* distb = dist + (size_t)bh * N_ * N_;
#pragma unroll
    for (int rr = 0; rr < 4; rr++) {
        int r = wid + rr * 8;
        float* srow = sc + r * SCP;
        float mx = -3.402823466e38f;
        for (int c = lane; c < 1024; c += 32) mx = fmaxf(mx, srow[c]);
#pragma unroll
        for (int o = 16; o; o >>= 1) mx = fmaxf(mx, __shfl_xor_sync(0xffffffffu, mx, o));
        float s = 0.f;
        for (int c = lane; c < 1024; c += 32) {
            float e = __expf(srow[c] - mx);
            srow[c] = e;
            s += e;
        }
#pragma unroll
        for (int o = 16; o; o >>= 1) s += __shfl_xor_sync(0xffffffffu, s, o);
        float inv = 1.0f / s;
        const float* arow = adj + (size_t)(n0 + r) * 1024;
        float* drow = distb + (size_t)(n0 + r) * 1024;
        for (int c = lane; c < 1024; c += 32) {
            float p = srow[c] * inv * arow[c];
            srow[c] = p;
            drow[c] = p;
        }
    }

    // ---- phase 3: att = P . V, double-buffered V ----
    float acc[2][8][4] = {};
    for (int vt = 0; vt < 8; vt++) {
        if (vt < 7) {
            __syncthreads();
            STAGE_V(vt + 1, (vt + 1) & 1); CPC(); CPW(1);
        } else {
            CPW(0);
        }
        __syncthreads();
        const uint32_t* Vhc = KhB[vt & 1];
        const uint32_t* Vlc = KlB[vt & 1];
        int kg = vt * 128 + wid * 16;
        uint32_t ah[2][4], alo[2][4];
#pragma unroll
        for (int mf = 0; mf < 2; mf++) {
            int r0 = (mf * 16 + qr) * SCP + kg;
            int r1 = (mf * 16 + qr + 8) * SCP + kg;
            float2 s0 = *(const float2*)&sc[r0 + 2 * qc];
            float2 s1 = *(const float2*)&sc[r1 + 2 * qc];
            float2 s2 = *(const float2*)&sc[r0 + 2 * qc + 8];
            float2 s3 = *(const float2*)&sc[r1 + 2 * qc + 8];
            h2split(s0.x, s0.y, ah[mf][0], alo[mf][0]);
            h2split(s1.x, s1.y, ah[mf][1], alo[mf][1]);
            h2split(s2.x, s2.y, ah[mf][2], alo[mf][2]);
            h2split(s3.x, s3.y, ah[mf][3], alo[mf][3]);
        }
#pragma unroll
        for (int nf = 0; nf < 8; nf++) {
            int rn = (nf * 8 + qr) * VST + wid * 8 + qc;
            uint32_t bhf[2], blf[2];
            bhf[0] = Vhc[rn];     bhf[1] = Vhc[rn + 4];
            blf[0] = Vlc[rn];     blf[1] = Vlc[rn + 4];
#pragma unroll
            for (int mf = 0; mf < 2; mf++) {
                mma16(acc[mf][nf], ah[mf], bhf);
                mma16(acc[mf][nf], ah[mf], blf);
                mma16(acc[mf][nf], alo[mf], bhf);
            }
        }
    }
    __syncthreads();

    // ---- cross-warp reduction of partial att ----
    float* part = (float*)su;    // 8 * 2048 floats, prior data dead
#pragma unroll
    for (int mf = 0; mf < 2; mf++)
#pragma unroll
        for (int nf = 0; nf < 8; nf++) {
            int row0 = mf * 16 + qr;
            int col = nf * 8 + 2 * qc;
            part[wid * 2048 + row0 * 64 + col]           = acc[mf][nf][0];
            part[wid * 2048 + row0 * 64 + col + 1]       = acc[mf][nf][1];
            part[wid * 2048 + (row0 + 8) * 64 + col]     = acc[mf][nf][2];
            part[wid * 2048 + (row0 + 8) * 64 + col + 1] = acc[mf][nf][3];
        }
    __syncthreads();
#pragma unroll
    for (int u = 0; u < 8; u++) {
        int idx = tid + u * 256;
        float s = 0.f;
#pragma unroll
        for (int w = 0; w < 8; w++) s += part[w * 2048 + idx];
        int row = idx >> 6, col = idx & 63;
        att[(size_t)(b * N_ + n0 + row) * 512 + h * 64 + col] = s;
    }
}

// ---------------- launch ----------------
extern "C" void kernel_launch(void* const* d_in, const int* in_sizes, int n_in,
                              void* d_out, int out_size) {
    const float* user_exo = (const float*)d_in[0];
    const float* exo      = (const float*)d_in[1];
    const float* adj      = (const float*)d_in[2];
    const float* Wq       = (const float*)d_in[3];
    const float* bq       = (const float*)d_in[4];
    const float* Wk       = (const float*)d_in[5];
    const float* bk       = (const float*)d_in[6];
    const float* Wv       = (const float*)d_in[7];
    const float* bv       = (const float*)d_in[8];
    const float* gamma    = (const float*)d_in[9];
    const float* beta     = (const float*)d_in[10];

    float* att  = (float*)d_out;                       // [B, N, DV]
    float* dist = att + (size_t)B_ * N_ * D_;          // [B, NH, N, N]

    const int gemm_smem = 4 * 128 * GST * (int)sizeof(uint32_t);   // 73728
    const int attn_smem = (2 * 32 * QST + 4 * 128 * KST) * (int)sizeof(uint32_t)
                        + 32 * SCP * (int)sizeof(float);           // 215552
    cudaFuncSetAttribute(gemm_qkv_tc, cudaFuncAttributeMaxDynamicSharedMemorySize, gemm_smem);
    cudaFuncSetAttribute(attn_tc, cudaFuncAttributeMaxDynamicSharedMemorySize, attn_smem);

    ln_prep<<<M_, 256>>>(user_exo, exo, gamma, beta);
    w_cvt<<<dim3(512, 3), 256>>>(Wq, Wk, Wv);
    gemm_qkv_tc<<<dim3(4, 32, 3), 256, gemm_smem>>>(bq, bk, bv);
    convert_v<<<dim3(8, 32), 256>>>();
    attn_tc<<<dim3(N_ / 32, NH_, B_), 256, attn_smem>>>(adj, att, dist);
}